// round 3
// baseline (speedup 1.0000x reference)
#include <cuda_runtime.h>
#include <cuda_bf16.h>

// ---------------------------------------------------------------------------
// Compile-time algebra tables for Cl(3,0,1)  (device-constexpr so device code
// can fold them without --expt-relaxed-constexpr)
// ---------------------------------------------------------------------------
__host__ __device__ constexpr int PC4(int x) {
    return ((x >> 0) & 1) + ((x >> 1) & 1) + ((x >> 2) & 1) + ((x >> 3) & 1);
}

__host__ __device__ constexpr float SGN(int a, int b) {
    int s = 0;
    int aa = a >> 1;
    while (aa) { s += PC4(aa & b); aa >>= 1; }
    return (s & 1) ? -1.0f : 1.0f;
}

struct GPTab { int a[192]; int b[192]; int k[192]; float s[192]; };
__host__ __device__ constexpr GPTab make_gp() {
    GPTab t{};
    int n = 0;
    for (int a = 0; a < 16; a++)
        for (int b = 0; b < 16; b++)
            if (!(a & b & 1)) {
                t.a[n] = a; t.b[n] = b; t.k[n] = a ^ b; t.s[n] = SGN(a, b);
                n++;
            }
    return t;
}

struct JTab { int a[81]; int b[81]; int k[81]; float s[81]; };
__host__ __device__ constexpr JTab make_j() {
    // J[i,j,k] = D[p,i] D[q,j] OP[p,q,r] D[r,k], D a signed permutation:
    // nonzero iff i|j == 15, with k = i&j.
    JTab t{};
    int n = 0;
    for (int i = 0; i < 16; i++)
        for (int j = 0; j < 16; j++)
            if ((i | j) == 15) {
                int p = i ^ 15, q = j ^ 15, k = i & j, r = k ^ 15;
                t.a[n] = i; t.b[n] = j; t.k[n] = k;
                t.s[n] = SGN(i, p) * SGN(j, q) * SGN(p, q) * SGN(k, r);
                n++;
            }
    return t;
}

__device__ constexpr GPTab GPT = make_gp();
__device__ constexpr JTab  JT  = make_j();
__device__ constexpr int PCY[16] = {0,1,1,2,1,2,2,3,1,2,2,3,2,3,3,4};

// ---------------------------------------------------------------------------
// Fused kernel
//   grid.y = 4 groups: (branch = gp|join) x (channel half)
//   Each block: 2 weight sets for 32 channels resident in smem (147 KB),
//   streams 32-position chunks, fuses equi_linear + bilinear + store.
//   Threads: 256 = 32 channels x 8 position slots; 4 positions per thread.
// ---------------------------------------------------------------------------
#define THREADS 256
#define WS_FLOATS (2 * 9 * 64 * 32)   // 36864
#define XS_FLOATS (32 * 8 * 16)       // 4096

__global__ __launch_bounds__(THREADS, 1)
void gbl_kernel(const float* __restrict__ x, const float* __restrict__ ref,
                const float* __restrict__ wg1, const float* __restrict__ wg2,
                const float* __restrict__ wj1, const float* __restrict__ wj2,
                float* __restrict__ out, int nPos)
{
    extern __shared__ float sm[];
    float* ws = sm;                 // [2][9][64][32]
    float* xs = sm + WS_FLOATS;     // [32 pp][8 iq][16 comp]

    const int tid   = threadIdx.x;
    const int c     = tid & 31;
    const int pslot = tid >> 5;
    const int group  = blockIdx.y;
    const int branch = group >> 1;   // 0 = gp, 1 = join
    const int chalf  = group & 1;

    const float* wA = branch ? wj1 : wg1;
    const float* wB = branch ? wj2 : wg2;

    // --- Load this block's weight slices into smem (contiguous 18432 floats each) ---
    {
        const float* srcA = wA + chalf * 32 * 576;   // w[j][i][b], j in [chalf*32, +32)
        const float* srcB = wB + chalf * 32 * 576;
        for (int e = tid; e < 18432; e += THREADS) {
            int cc  = e / 576;
            int rem = e - cc * 576;
            int ii  = rem / 9;
            int bb  = rem - ii * 9;
            ws[(bb * 64 + ii) * 32 + cc]        = srcA[e];
            ws[((9 + bb) * 64 + ii) * 32 + cc]  = srcB[e];
        }
    }
    __syncthreads();

    const int cout = branch * 64 + chalf * 32 + c;
    const int nChunk = nPos >> 5;   // 32 positions per chunk
    const float4* xb4 = (const float4*)x;

    for (int chunk = blockIdx.x; chunk < nChunk; chunk += gridDim.x) {
        const int p0 = chunk << 5;

        float Ea[4][16];
        float Eb[4][16];
        #pragma unroll
        for (int np = 0; np < 4; np++)
            #pragma unroll
            for (int y = 0; y < 16; y++) { Ea[np][y] = 0.0f; Eb[np][y] = 0.0f; }

        // Prefetch i-chunk 0 (4 float4 per thread)
        float4 pf[4];
        #pragma unroll
        for (int k = 0; k < 4; k++) {
            int f = tid + k * THREADS;
            int pp = f >> 5, off = f & 31;
            pf[k] = xb4[(size_t)(p0 + pp) * 256 + off];   // ic = 0
        }

        for (int ic = 0; ic < 64; ic += 8) {
            __syncthreads();
            #pragma unroll
            for (int k = 0; k < 4; k++)
                ((float4*)xs)[tid + k * THREADS] = pf[k];
            __syncthreads();

            if (ic < 56) {
                #pragma unroll
                for (int k = 0; k < 4; k++) {
                    int f = tid + k * THREADS;
                    int pp = f >> 5, off = f & 31;
                    pf[k] = xb4[(size_t)(p0 + pp) * 256 + (ic + 8) * 4 + off];
                }
            }

            #pragma unroll 2
            for (int iq = 0; iq < 8; iq++) {
                const int i = ic + iq;
                float wa[9], wb[9];
                #pragma unroll
                for (int b = 0; b < 9; b++) {
                    wa[b] = ws[(b * 64 + i) * 32 + c];
                    wb[b] = ws[((9 + b) * 64 + i) * 32 + c];
                }
                #pragma unroll
                for (int np = 0; np < 4; np++) {
                    const float* xv = xs + ((pslot * 4 + np) * 8 + iq) * 16;
                    float4 q0 = *(const float4*)(xv + 0);
                    float4 q1 = *(const float4*)(xv + 4);
                    float4 q2 = *(const float4*)(xv + 8);
                    float4 q3 = *(const float4*)(xv + 12);
                    float v[16] = {q0.x, q0.y, q0.z, q0.w,
                                   q1.x, q1.y, q1.z, q1.w,
                                   q2.x, q2.y, q2.z, q2.w,
                                   q3.x, q3.y, q3.z, q3.w};
                    #pragma unroll
                    for (int y = 0; y < 16; y++) {
                        Ea[np][y] += wa[PCY[y]] * v[y];
                        Eb[np][y] += wb[PCY[y]] * v[y];
                        if (y & 1) {
                            Ea[np][y] += wa[4 + PCY[y]] * v[y ^ 1];
                            Eb[np][y] += wb[4 + PCY[y]] * v[y ^ 1];
                        }
                    }
                }
            }
        }

        // --- Bilinear + store ---
        #pragma unroll
        for (int np = 0; np < 4; np++) {
            const int p = p0 + pslot * 4 + np;
            float o[16];
            #pragma unroll
            for (int y = 0; y < 16; y++) o[y] = 0.0f;

            if (branch == 0) {
                #pragma unroll
                for (int e = 0; e < 192; e++)
                    o[GPT.k[e]] += GPT.s[e] * Ea[np][GPT.a[e]] * Eb[np][GPT.b[e]];
                #pragma unroll
                for (int y = 0; y < 16; y++) o[y] *= 1e-5f;
            } else {
                const float r = __ldg(ref + (size_t)p * 16 + 15);
                #pragma unroll
                for (int e = 0; e < 81; e++)
                    o[JT.k[e]] += JT.s[e] * Ea[np][JT.a[e]] * Eb[np][JT.b[e]];
                #pragma unroll
                for (int y = 0; y < 16; y++) o[y] *= r;
            }

            float4* op = (float4*)(out + ((size_t)p * 128 + cout) * 16);
            op[0] = make_float4(o[0],  o[1],  o[2],  o[3]);
            op[1] = make_float4(o[4],  o[5],  o[6],  o[7]);
            op[2] = make_float4(o[8],  o[9],  o[10], o[11]);
            op[3] = make_float4(o[12], o[13], o[14], o[15]);
        }
    }
}

// ---------------------------------------------------------------------------
extern "C" void kernel_launch(void* const* d_in, const int* in_sizes, int n_in,
                              void* d_out, int out_size) {
    const float* x   = (const float*)d_in[0];
    const float* ref = (const float*)d_in[1];
    const float* wg1 = (const float*)d_in[2];
    const float* wg2 = (const float*)d_in[3];
    const float* wj1 = (const float*)d_in[4];
    const float* wj2 = (const float*)d_in[5];
    float* out = (float*)d_out;

    const int nPos = in_sizes[0] / (64 * 16);   // 16384

    const int smem = (WS_FLOATS + XS_FLOATS) * sizeof(float);   // 160 KB
    cudaFuncSetAttribute(gbl_kernel, cudaFuncAttributeMaxDynamicSharedMemorySize, smem);

    dim3 grid(37, 4);   // 148 blocks = 1 wave at 1 block/SM
    gbl_kernel<<<grid, THREADS, smem>>>(x, ref, wg1, wg2, wj1, wj2, out, nPos);
}